// round 16
// baseline (speedup 1.0000x reference)
#include <cuda_runtime.h>
#include <cuda_bf16.h>
#include <cstdint>
#include <cstddef>

#define AZf (-999999.0f)
static const int NMAXC = 100000;

// Scratch (no cudaMalloc allowed)
__device__ __nv_bfloat16 g_h1[(size_t)NMAXC * 256];
__device__ __nv_bfloat16 g_h2[(size_t)NMAXC * 256];
__device__ __nv_bfloat16 g_Wt1[256 * 768];
__device__ __nv_bfloat16 g_Wt2[256 * 256];
__device__ __nv_bfloat16 g_Wet[256 * 512];

// ---------------- helpers ----------------
__device__ __forceinline__ uint32_t smem_u32(const void* p) {
    uint32_t a;
    asm("{ .reg .u64 t; cvta.to.shared.u64 t, %1; cvt.u32.u64 %0, t; }" : "=r"(a) : "l"(p));
    return a;
}
__device__ __forceinline__ void ldsm4(uint32_t& r0, uint32_t& r1, uint32_t& r2, uint32_t& r3, uint32_t addr) {
    asm volatile("ldmatrix.sync.aligned.m8n8.x4.shared.b16 {%0,%1,%2,%3}, [%4];"
                 : "=r"(r0), "=r"(r1), "=r"(r2), "=r"(r3) : "r"(addr));
}
__device__ __forceinline__ void mma_bf16(float* c, const uint32_t* a, uint32_t b0, uint32_t b1) {
    asm volatile("mma.sync.aligned.m16n8k16.row.col.f32.bf16.bf16.f32 "
                 "{%0,%1,%2,%3}, {%4,%5,%6,%7}, {%8,%9}, {%0,%1,%2,%3};"
                 : "+f"(c[0]), "+f"(c[1]), "+f"(c[2]), "+f"(c[3])
                 : "r"(a[0]), "r"(a[1]), "r"(a[2]), "r"(a[3]), "r"(b0), "r"(b1));
}
__device__ __forceinline__ uint32_t pack_bf16(float lo, float hi) {
    __nv_bfloat162 h = __floats2bfloat162_rn(lo, hi);
    return *reinterpret_cast<uint32_t*>(&h);
}
__device__ __forceinline__ void cp16(uint32_t dst, const void* src) {
    asm volatile("cp.async.cg.shared.global [%0], [%1], 16;" :: "r"(dst), "l"(src));
}
__device__ __forceinline__ void cp16z(uint32_t dst, const void* src, int srcsz) {
    asm volatile("cp.async.cg.shared.global [%0], [%1], 16, %2;" :: "r"(dst), "l"(src), "r"(srcsz));
}
#define CP_COMMIT() asm volatile("cp.async.commit_group;" ::: "memory")
#define CP_WAIT1()  asm volatile("cp.async.wait_group 1;" ::: "memory")
#define CP_WAIT0()  asm volatile("cp.async.wait_group 0;" ::: "memory")

// SMEM rows: 32 bf16 (64B payload) at 80B stride -> conflict-free ldmatrix
#define RSTR   80
#define TA     10240    // 128-row tile
#define TBW    20480    // 256-row tile (wide B)
// hgemm1 (512 thr): A double (reg-staged) + wide-B triple
#define W1_A(b) ((uint32_t)((b) * TA))
#define W1_B(b) ((uint32_t)(2 * TA + (b) * TBW))
#define SMEM_W1 (2 * TA + 3 * TBW)           // 81920
// hgemm2 (512 thr): A triple + wide-B triple
#define W2_A(b) ((uint32_t)((b) * TA))
#define W2_B(b) ((uint32_t)(3 * TA + (b) * TBW))
#define SMEM_W2 (3 * TA + 3 * TBW)           // 92160
// edge (256 thr): A triple + B triple (128-row)
#define E_A(b) ((uint32_t)((b) * TA))
#define E_B(b) ((uint32_t)((3 + (b)) * TA))
#define SMEM_E (6 * TA)                      // 61440

// ---------------------------------------------------------------------------
// Transpose + fp32->bf16: Wt[n][k] = bf16(W[k][n])
// ---------------------------------------------------------------------------
__global__ void transpose_w(const float* __restrict__ W, __nv_bfloat16* __restrict__ Wt, int K, int N) {
    __shared__ float t[32][33];
    int k0 = blockIdx.y * 32, n0 = blockIdx.x * 32;
    int x = threadIdx.x, y = threadIdx.y;
#pragma unroll
    for (int i = 0; i < 32; i += 8) {
        int k = k0 + y + i, n = n0 + x;
        t[y + i][x] = (k < K && n < N) ? W[(size_t)k * N + n] : 0.f;
    }
    __syncthreads();
#pragma unroll
    for (int i = 0; i < 32; i += 8) {
        int n = n0 + y + i, k = k0 + x;
        if (n < N && k < K) Wt[(size_t)n * K + k] = __float2bfloat16(t[x][y + i]);
    }
}

// ---------------- warp-level GEMM core (warp 32x64, K-chunk 32) ----------
struct Frag { float acc[2][8][4]; };

__device__ __forceinline__ void frag_zero(Frag& f) {
#pragma unroll
    for (int i = 0; i < 2; i++)
#pragma unroll
        for (int j = 0; j < 8; j++)
#pragma unroll
            for (int l = 0; l < 4; l++) f.acc[i][j][l] = 0.f;
}

__device__ __forceinline__ void core_compute(
    Frag& f, uint32_t sbase, uint32_t aOff, uint32_t bOff,
    int warp_m, int warp_n, int lane)
{
    const uint32_t aBase = sbase + aOff + (warp_m + (lane & 15)) * RSTR + ((lane >> 4) << 4);
    const uint32_t bBase = sbase + bOff + (warp_n + (lane & 7) + ((lane >> 4) << 3)) * RSTR
                           + (((lane >> 3) & 1) << 4);
#pragma unroll
    for (int ks = 0; ks < 2; ks++) {
        uint32_t a[2][4];
        ldsm4(a[0][0], a[0][1], a[0][2], a[0][3], aBase + ks * 32);
        ldsm4(a[1][0], a[1][1], a[1][2], a[1][3], aBase + 16 * RSTR + ks * 32);
        uint32_t b[4][4];
#pragma unroll
        for (int np = 0; np < 4; np++)
            ldsm4(b[np][0], b[np][1], b[np][2], b[np][3], bBase + np * 16 * RSTR + ks * 32);
#pragma unroll
        for (int mt = 0; mt < 2; mt++)
#pragma unroll
            for (int nt = 0; nt < 8; nt++) {
                const int np = nt >> 1, hb = (nt & 1) << 1;
                mma_bf16(f.acc[mt][nt], a[mt], b[np][hb], b[np][hb + 1]);
            }
    }
}

// ---------------------------------------------------------------------------
// GEMM1 (512 thr, CTA 128x256): C = bf16(relu(A_fp32[M,K] @ Bt[256,K]^T + b))
// A: LDG fp32 -> cvt -> STS (2-stage, hoisted LDG); B: cp.async 3-stage.
// ---------------------------------------------------------------------------
__global__ __launch_bounds__(512) void hgemm1(
    const float* __restrict__ A, const __nv_bfloat16* __restrict__ Bt,
    const float* __restrict__ bias, __nv_bfloat16* __restrict__ C,
    int M, int K)
{
    extern __shared__ uint8_t smem[];
    const uint32_t sbase = smem_u32(smem);
    const int tid = threadIdx.x, lane = tid & 31, wid = tid >> 5;
    const int mBase = blockIdx.x << 7;
    const int warp_m = (wid & 3) << 5, warp_n = (wid >> 2) << 6;

    // A loader: 512 thr, each 8 fp32 of a 128x32 tile
    const int alr = tid >> 2, akq = tid & 3;           // row, quarter
    const bool mv = (mBase + alr) < M;
    const float* aRow = A + (size_t)(mBase + alr) * K + akq * 8;
    // B loader: 512 thr, each 16 bf16 of a 256x32 tile
    const int blr = tid >> 1, bkh = tid & 1;
    const __nv_bfloat16* bRow = Bt + (size_t)blr * K + bkh * 16;

    Frag f; frag_zero(f);

    uint32_t aR[4];
    auto ldgA = [&](int c) {
        if (!mv) { aR[0] = aR[1] = aR[2] = aR[3] = 0; return; }
        const float4* p = (const float4*)(aRow + (c << 5));
        float4 f0 = p[0], f1 = p[1];
        aR[0] = pack_bf16(f0.x, f0.y); aR[1] = pack_bf16(f0.z, f0.w);
        aR[2] = pack_bf16(f1.x, f1.y); aR[3] = pack_bf16(f1.z, f1.w);
    };
    auto stsA = [&](int buf) {
        uint8_t* sa = smem + W1_A(buf) + alr * RSTR + akq * 16;
        *(uint4*)sa = make_uint4(aR[0], aR[1], aR[2], aR[3]);
    };
    auto issueB = [&](int c, int buf) {
        uint32_t d = sbase + W1_B(buf) + blr * RSTR + bkh * 32;
        const __nv_bfloat16* s = bRow + (c << 5);
        cp16(d, s); cp16(d + 16, s + 8);
    };

    ldgA(0); stsA(0);
    issueB(0, 0); CP_COMMIT();
    issueB(1, 1); CP_COMMIT();
    __syncthreads();

    const int NC = K >> 5;
    for (int c = 0; c < NC; c++) {
        if (c + 1 < NC) ldgA(c + 1);                   // hoisted prefetch
        if (c == NC - 1) CP_WAIT0(); else CP_WAIT1();
        __syncthreads();
        if (c + 2 < NC) { issueB(c + 2, (c + 2) % 3); CP_COMMIT(); }
        core_compute(f, sbase, W1_A(c & 1), W1_B(c % 3), warp_m, warp_n, lane);
        if (c + 1 < NC) stsA((c + 1) & 1);
    }

#pragma unroll
    for (int mt = 0; mt < 2; mt++) {
        const int r0 = mBase + warp_m + mt * 16 + (lane >> 2);
#pragma unroll
        for (int nt = 0; nt < 8; nt++) {
            const int col = warp_n + nt * 8 + ((lane & 3) << 1);
            const float b0 = bias[col], b1 = bias[col + 1];
            if (r0 < M)
                *(uint32_t*)(C + (size_t)r0 * 256 + col) =
                    pack_bf16(fmaxf(f.acc[mt][nt][0] + b0, 0.f), fmaxf(f.acc[mt][nt][1] + b1, 0.f));
            if (r0 + 8 < M)
                *(uint32_t*)(C + (size_t)(r0 + 8) * 256 + col) =
                    pack_bf16(fmaxf(f.acc[mt][nt][2] + b0, 0.f), fmaxf(f.acc[mt][nt][3] + b1, 0.f));
        }
    }
}

// ---------------------------------------------------------------------------
// GEMM2 (512 thr, CTA 128x256): C = bf16(relu(A_bf16[M,256] @ Bt[256,256]^T + b))
// Full cp.async 3-stage on A and B.
// ---------------------------------------------------------------------------
__global__ __launch_bounds__(512) void hgemm2(
    const __nv_bfloat16* __restrict__ A, const __nv_bfloat16* __restrict__ Bt,
    const float* __restrict__ bias, __nv_bfloat16* __restrict__ C,
    int M, int K)
{
    extern __shared__ uint8_t smem[];
    const uint32_t sbase = smem_u32(smem);
    const int tid = threadIdx.x, lane = tid & 31, wid = tid >> 5;
    const int mBase = blockIdx.x << 7;
    const int warp_m = (wid & 3) << 5, warp_n = (wid >> 2) << 6;

    const int alr = tid >> 2, akq = tid & 3;
    const int asz = ((mBase + alr) < M) ? 16 : 0;
    const __nv_bfloat16* aRow = A + (size_t)(mBase + alr) * K + akq * 8;
    const int blr = tid >> 1, bkh = tid & 1;
    const __nv_bfloat16* bRow = Bt + (size_t)blr * K + bkh * 16;

    Frag f; frag_zero(f);

    auto issueAB = [&](int c, int buf) {
        uint32_t da = sbase + W2_A(buf) + alr * RSTR + akq * 16;
        cp16z(da, aRow + (c << 5), asz);
        uint32_t db = sbase + W2_B(buf) + blr * RSTR + bkh * 32;
        const __nv_bfloat16* sb = bRow + (c << 5);
        cp16(db, sb); cp16(db + 16, sb + 8);
    };

    issueAB(0, 0); CP_COMMIT();
    issueAB(1, 1); CP_COMMIT();

    const int NC = K >> 5;
    for (int c = 0; c < NC; c++) {
        if (c == NC - 1) CP_WAIT0(); else CP_WAIT1();
        __syncthreads();
        if (c + 2 < NC) { issueAB(c + 2, (c + 2) % 3); CP_COMMIT(); }
        core_compute(f, sbase, W2_A(c % 3), W2_B(c % 3), warp_m, warp_n, lane);
    }

#pragma unroll
    for (int mt = 0; mt < 2; mt++) {
        const int r0 = mBase + warp_m + mt * 16 + (lane >> 2);
#pragma unroll
        for (int nt = 0; nt < 8; nt++) {
            const int col = warp_n + nt * 8 + ((lane & 3) << 1);
            const float b0 = bias[col], b1 = bias[col + 1];
            if (r0 < M)
                *(uint32_t*)(C + (size_t)r0 * 256 + col) =
                    pack_bf16(fmaxf(f.acc[mt][nt][0] + b0, 0.f), fmaxf(f.acc[mt][nt][1] + b1, 0.f));
            if (r0 + 8 < M)
                *(uint32_t*)(C + (size_t)(r0 + 8) * 256 + col) =
                    pack_bf16(fmaxf(f.acc[mt][nt][2] + b0, 0.f), fmaxf(f.acc[mt][nt][3] + b1, 0.f));
        }
    }
}

// ---------------------------------------------------------------------------
// Edge GEMM (256 thr, CTA 128x128): gathered A, cp.async 3-stage, CRF mask.
// ---------------------------------------------------------------------------
__global__ __launch_bounds__(256) void hgemm_edge(
    const __nv_bfloat16* __restrict__ h, const __nv_bfloat16* __restrict__ Bt,
    const float* __restrict__ be,
    const int* __restrict__ parent, const int* __restrict__ child,
    const int* __restrict__ obs, const int* __restrict__ tl,
    float* __restrict__ out, int E)
{
    extern __shared__ uint8_t smem[];
    __shared__ int sPl[128], sCl[128], sOp[128], sOc[128];
    const uint32_t sbase = smem_u32(smem);
    const int tid = threadIdx.x, lane = tid & 31, wid = tid >> 5;
    const int mBase = blockIdx.y << 7, nBase = blockIdx.x << 7;
    const int warp_m = (wid & 3) << 5, warp_n = (wid >> 2) << 6;

    const int lr = tid >> 1, kh = (tid & 1) << 4;
    const int eA = mBase + lr;
    const bool ev = eA < E;
    const int asz = ev ? 16 : 0;
    const int pidx = ev ? parent[eA] : 0;
    const int cidx = ev ? child[eA] : 0;
    const __nv_bfloat16* pRow = h + (size_t)pidx * 256 + kh;
    const __nv_bfloat16* cRow = h + (size_t)cidx * 256 + kh;
    const __nv_bfloat16* bRow = Bt + (size_t)(nBase + lr) * 512 + kh;

    Frag f; frag_zero(f);

    auto issueAB = [&](int c, int buf) {
        uint32_t da = sbase + E_A(buf) + lr * RSTR + kh * 2;
        const __nv_bfloat16* sa = ((c < 8) ? pRow : cRow) + ((c & 7) << 5);
        cp16z(da, sa, asz); cp16z(da + 16, sa + 8, asz);
        uint32_t db = sbase + E_B(buf) + lr * RSTR + kh * 2;
        const __nv_bfloat16* sb = bRow + (c << 5);
        cp16(db, sb); cp16(db + 16, sb + 8);
    };

    issueAB(0, 0); CP_COMMIT();
    issueAB(1, 1); CP_COMMIT();

    const int NC = 16;  // K = 512
    for (int c = 0; c < NC; c++) {
        if (c == NC - 1) CP_WAIT0(); else CP_WAIT1();
        __syncthreads();
        if (c + 2 < NC) { issueAB(c + 2, (c + 2) % 3); CP_COMMIT(); }
        core_compute(f, sbase, E_A(c % 3), E_B(c % 3), warp_m, warp_n, lane);
    }

    if (tid < 128) {
        int e = mBase + tid;
        int pi = 0, ci = 0;
        if (e < E) { pi = parent[e]; ci = child[e]; }
        sPl[tid] = tl[pi]; sCl[tid] = tl[ci];
        sOp[tid] = obs[pi]; sOc[tid] = obs[ci];
    }
    __syncthreads();

    auto maskv = [&](float ep, int rloc, int rl, int cb) -> float {
        const int pl = sPl[rloc], cl = sCl[rloc];
        const int op = sOp[rloc], oc = sOc[rloc];
        if (op && oc) return (rl == pl && cb == cl) ? 0.f : AZf;
        if (oc)       return ep + ((rl == cl) ? 0.f : AZf);
        if (op)       return ep + ((cb == pl) ? 0.f : AZf);
        return ep;
    };

#pragma unroll
    for (int mt = 0; mt < 2; mt++) {
        const int rloc0 = warp_m + mt * 16 + (lane >> 2);
#pragma unroll
        for (int nt = 0; nt < 8; nt++) {
            const int col = nBase + warp_n + nt * 8 + ((lane & 3) << 1);
            const int rl = col >> 4, cb = col & 15;
            const int rl1 = (col + 1) >> 4, cb1 = (col + 1) & 15;
            const float b0 = be[col], b1 = be[col + 1];
            if (mBase + rloc0 < E) {
                float2 v;
                v.x = maskv(f.acc[mt][nt][0] + b0, rloc0, rl, cb);
                v.y = maskv(f.acc[mt][nt][1] + b1, rloc0, rl1, cb1);
                *(float2*)(out + (size_t)(mBase + rloc0) * 256 + col) = v;
            }
            if (mBase + rloc0 + 8 < E) {
                float2 v;
                v.x = maskv(f.acc[mt][nt][2] + b0, rloc0 + 8, rl, cb);
                v.y = maskv(f.acc[mt][nt][3] + b1, rloc0 + 8, rl1, cb1);
                *(float2*)(out + (size_t)(mBase + rloc0 + 8) * 256 + col) = v;
            }
        }
    }
}

// ---------------------------------------------------------------------------
// Unary: vectorized uint4 loads of h2.
// ---------------------------------------------------------------------------
__global__ __launch_bounds__(256) void unary_kernel(
    const __nv_bfloat16* __restrict__ h, const float* __restrict__ Wu,
    const float* __restrict__ bu, const int* __restrict__ obs,
    const int* __restrict__ tl, float* __restrict__ out, int N)
{
    __shared__ float sW[256 * 16];
    __shared__ float sH[16][260];
    const int tid = threadIdx.x;
    const float4* w4 = (const float4*)Wu;
    for (int i = tid; i < 1024; i += 256) ((float4*)sW)[i] = w4[i];
    const int row0 = blockIdx.x * 16;
    for (int i = tid; i < 512; i += 256) {
        const int r = i >> 5;
        const int c8 = (i & 31) << 3;
        uint4 v = make_uint4(0, 0, 0, 0);
        if (row0 + r < N)
            v = ((const uint4*)(h + (size_t)(row0 + r) * 256))[i & 31];
        uint32_t u[4] = {v.x, v.y, v.z, v.w};
#pragma unroll
        for (int j = 0; j < 4; j++) {
            __nv_bfloat162 b2 = *reinterpret_cast<__nv_bfloat162*>(&u[j]);
            sH[r][c8 + 2 * j]     = __bfloat162float(b2.x);
            sH[r][c8 + 2 * j + 1] = __bfloat162float(b2.y);
        }
    }
    __syncthreads();
    const int tx = tid & 15, ty = tid >> 4;
    const int row = row0 + ty;
    if (row >= N) return;
    float acc = 0.f;
#pragma unroll 8
    for (int k = 0; k < 256; k++) acc += sH[ty][k] * sW[k * 16 + tx];
    float v;
    if (obs[row]) v = (tl[row] == tx) ? 0.f : AZf;
    else          v = acc + bu[tx];
    out[(size_t)row * 16 + tx] = v;
}

// ---------------------------------------------------------------------------

extern "C" void kernel_launch(void* const* d_in, const int* in_sizes, int n_in,
                              void* d_out, int out_size)
{
    const float* features = (const float*)d_in[0];
    const int*   parent   = (const int*)  d_in[1];
    const int*   child    = (const int*)  d_in[2];
    const int*   obs      = (const int*)  d_in[3];
    const int*   tl       = (const int*)  d_in[4];
    const float* W1       = (const float*)d_in[5];
    const float* b1       = (const float*)d_in[6];
    const float* W2       = (const float*)d_in[7];
    const float* b2       = (const float*)d_in[8];
    const float* Wu       = (const float*)d_in[9];
    const float* bu       = (const float*)d_in[10];
    const float* We       = (const float*)d_in[11];
    const float* be       = (const float*)d_in[12];

    const int N = in_sizes[0] / 768;
    const int E = in_sizes[1];

    float* outU = (float*)d_out;
    float* outE = outU + (size_t)N * 16;

    __nv_bfloat16 *h1, *h2, *wt1, *wt2, *wet;
    cudaGetSymbolAddress((void**)&h1,  g_h1);
    cudaGetSymbolAddress((void**)&h2,  g_h2);
    cudaGetSymbolAddress((void**)&wt1, g_Wt1);
    cudaGetSymbolAddress((void**)&wt2, g_Wt2);
    cudaGetSymbolAddress((void**)&wet, g_Wet);

    cudaFuncSetAttribute(hgemm1,     cudaFuncAttributeMaxDynamicSharedMemorySize, SMEM_W1);
    cudaFuncSetAttribute(hgemm2,     cudaFuncAttributeMaxDynamicSharedMemorySize, SMEM_W2);
    cudaFuncSetAttribute(hgemm_edge, cudaFuncAttributeMaxDynamicSharedMemorySize, SMEM_E);

    // Side stream + events, created once on the first (non-capture) call.
    static cudaStream_t s2 = nullptr;
    static cudaEvent_t ev1 = nullptr, ev2 = nullptr;
    if (!s2) {
        cudaStreamCreateWithFlags(&s2, cudaStreamNonBlocking);
        cudaEventCreateWithFlags(&ev1, cudaEventDisableTiming);
        cudaEventCreateWithFlags(&ev2, cudaEventDisableTiming);
    }

    const int gM = (N + 127) / 128;
    const int gE = (E + 127) / 128;

    transpose_w<<<dim3(8, 24), dim3(32, 8)>>>(W1, wt1, 768, 256);
    transpose_w<<<dim3(8, 8),  dim3(32, 8)>>>(W2, wt2, 256, 256);
    transpose_w<<<dim3(8, 16), dim3(32, 8)>>>(We, wet, 512, 256);

    hgemm1<<<gM, 512, SMEM_W1>>>(features, wt1, b1, h1, N, 768);
    hgemm2<<<gM, 512, SMEM_W2>>>(h1, wt2, b2, h2, N, 256);
    cudaEventRecord(ev1, 0);

    // Fork: unary on s2 overlaps edge on main (both depend only on h2).
    cudaStreamWaitEvent(s2, ev1, 0);
    unary_kernel<<<(N + 15) / 16, 256, 0, s2>>>(h2, Wu, bu, obs, tl, outU, N);
    cudaEventRecord(ev2, s2);

    hgemm_edge<<<dim3(2, gE), 256, SMEM_E>>>(h2, wet, be, parent, child, obs, tl, outE, E);
    cudaStreamWaitEvent(0, ev2, 0);     // join before harness's end-of-capture
}

// round 17
// speedup vs baseline: 1.0936x; 1.0936x over previous
#include <cuda_runtime.h>
#include <cuda_bf16.h>
#include <cstdint>
#include <cstddef>

#define AZf (-999999.0f)
static const int NMAXC = 100000;

// Scratch (no cudaMalloc allowed)
__device__ __nv_bfloat16 g_h1[(size_t)NMAXC * 256];
__device__ __nv_bfloat16 g_h2[(size_t)NMAXC * 256];
__device__ __nv_bfloat16 g_Wt1[256 * 768];
__device__ __nv_bfloat16 g_Wt2[256 * 256];
__device__ __nv_bfloat16 g_Wet[256 * 512];

// ---------------- helpers ----------------
__device__ __forceinline__ uint32_t smem_u32(const void* p) {
    uint32_t a;
    asm("{ .reg .u64 t; cvta.to.shared.u64 t, %1; cvt.u32.u64 %0, t; }" : "=r"(a) : "l"(p));
    return a;
}
__device__ __forceinline__ void ldsm4(uint32_t& r0, uint32_t& r1, uint32_t& r2, uint32_t& r3, uint32_t addr) {
    asm volatile("ldmatrix.sync.aligned.m8n8.x4.shared.b16 {%0,%1,%2,%3}, [%4];"
                 : "=r"(r0), "=r"(r1), "=r"(r2), "=r"(r3) : "r"(addr));
}
__device__ __forceinline__ void mma_bf16(float* c, const uint32_t* a, uint32_t b0, uint32_t b1) {
    asm volatile("mma.sync.aligned.m16n8k16.row.col.f32.bf16.bf16.f32 "
                 "{%0,%1,%2,%3}, {%4,%5,%6,%7}, {%8,%9}, {%0,%1,%2,%3};"
                 : "+f"(c[0]), "+f"(c[1]), "+f"(c[2]), "+f"(c[3])
                 : "r"(a[0]), "r"(a[1]), "r"(a[2]), "r"(a[3]), "r"(b0), "r"(b1));
}
__device__ __forceinline__ uint32_t pack_bf16(float lo, float hi) {
    __nv_bfloat162 h = __floats2bfloat162_rn(lo, hi);
    return *reinterpret_cast<uint32_t*>(&h);
}
__device__ __forceinline__ void cp16(uint32_t dst, const void* src) {
    asm volatile("cp.async.cg.shared.global [%0], [%1], 16;" :: "r"(dst), "l"(src));
}
__device__ __forceinline__ void cp16z(uint32_t dst, const void* src, int srcsz) {
    asm volatile("cp.async.cg.shared.global [%0], [%1], 16, %2;" :: "r"(dst), "l"(src), "r"(srcsz));
}
#define CP_COMMIT() asm volatile("cp.async.commit_group;" ::: "memory")
#define CP_WAIT1()  asm volatile("cp.async.wait_group 1;" ::: "memory")
#define CP_WAIT0()  asm volatile("cp.async.wait_group 0;" ::: "memory")

// SMEM rows: 32 bf16 (64B payload) at 80B stride -> conflict-free ldmatrix
#define RSTR   80
#define TILE_B 10240
// GEMM1: A double-buffer (reg-staged) at 0, TILE_B; B triple-buffer after
#define G1_A(b) ((uint32_t)((b) * TILE_B))
#define G1_B(b) ((uint32_t)((2 + (b)) * TILE_B))
#define SMEM_G1 (5 * TILE_B)
// GEMM2/edge: A triple + B triple
#define G2_A(b) ((uint32_t)((b) * TILE_B))
#define G2_B(b) ((uint32_t)((3 + (b)) * TILE_B))
#define SMEM_G2 (6 * TILE_B)

// ---------------------------------------------------------------------------
// Transpose + fp32->bf16: Wt[n][k] = bf16(W[k][n])
// ---------------------------------------------------------------------------
__global__ void transpose_w(const float* __restrict__ W, __nv_bfloat16* __restrict__ Wt, int K, int N) {
    __shared__ float t[32][33];
    int k0 = blockIdx.y * 32, n0 = blockIdx.x * 32;
    int x = threadIdx.x, y = threadIdx.y;
#pragma unroll
    for (int i = 0; i < 32; i += 8) {
        int k = k0 + y + i, n = n0 + x;
        t[y + i][x] = (k < K && n < N) ? W[(size_t)k * N + n] : 0.f;
    }
    __syncthreads();
#pragma unroll
    for (int i = 0; i < 32; i += 8) {
        int n = n0 + y + i, k = k0 + x;
        if (n < N && k < K) Wt[(size_t)n * K + k] = __float2bfloat16(t[x][y + i]);
    }
}

// ---------------- shared warp-level GEMM core (128x128 CTA, warp 32x64) ----
struct Frag { float acc[2][8][4]; };

__device__ __forceinline__ void frag_zero(Frag& f) {
#pragma unroll
    for (int i = 0; i < 2; i++)
#pragma unroll
        for (int j = 0; j < 8; j++)
#pragma unroll
            for (int l = 0; l < 4; l++) f.acc[i][j][l] = 0.f;
}

__device__ __forceinline__ void core_compute(
    Frag& f, uint32_t sbase, uint32_t aOff, uint32_t bOff,
    int warp_m, int warp_n, int lane)
{
    const uint32_t aBase = sbase + aOff + (warp_m + (lane & 15)) * RSTR + ((lane >> 4) << 4);
    const uint32_t bBase = sbase + bOff + (warp_n + (lane & 7) + ((lane >> 4) << 3)) * RSTR
                           + (((lane >> 3) & 1) << 4);
#pragma unroll
    for (int ks = 0; ks < 2; ks++) {
        uint32_t a[2][4];
        ldsm4(a[0][0], a[0][1], a[0][2], a[0][3], aBase + ks * 32);
        ldsm4(a[1][0], a[1][1], a[1][2], a[1][3], aBase + 16 * RSTR + ks * 32);
        uint32_t b[4][4];
#pragma unroll
        for (int np = 0; np < 4; np++)
            ldsm4(b[np][0], b[np][1], b[np][2], b[np][3], bBase + np * 16 * RSTR + ks * 32);
#pragma unroll
        for (int mt = 0; mt < 2; mt++)
#pragma unroll
            for (int nt = 0; nt < 8; nt++) {
                const int np = nt >> 1, hb = (nt & 1) << 1;
                mma_bf16(f.acc[mt][nt], a[mt], b[np][hb], b[np][hb + 1]);
            }
    }
}

// ---------------------------------------------------------------------------
// GEMM1: C[M,256] = bf16(relu(A_fp32[M,K] @ Bt[256,K]^T + bias))
// A: LDG fp32 -> convert -> STS (2-stage, LDG hoisted above pipeline wait);
// B: cp.async (3-stage); K-chunk 32.
// ---------------------------------------------------------------------------
__global__ __launch_bounds__(256) void hgemm1(
    const float* __restrict__ A, const __nv_bfloat16* __restrict__ Bt,
    const float* __restrict__ bias, __nv_bfloat16* __restrict__ C,
    int M, int K)
{
    extern __shared__ uint8_t smem[];
    const uint32_t sbase = smem_u32(smem);
    const int tid = threadIdx.x, lane = tid & 31, wid = tid >> 5;
    const int mBase = blockIdx.y << 7, nBase = blockIdx.x << 7;
    const int warp_m = (wid & 3) << 5, warp_n = (wid >> 2) << 6;

    const int lr = tid >> 1, kh = (tid & 1) << 4;
    const bool mv = (mBase + lr) < M;
    const float* aRow = A + (size_t)(mBase + lr) * K + kh;
    const __nv_bfloat16* bRow = Bt + (size_t)(nBase + lr) * K + kh;

    Frag f; frag_zero(f);

    uint32_t aR[8];
    auto ldgA = [&](int c) {
        if (!mv) {
#pragma unroll
            for (int i = 0; i < 8; i++) aR[i] = 0;
            return;
        }
        const float4* p = (const float4*)(aRow + (c << 5));
        float4 f0 = p[0], f1 = p[1], f2 = p[2], f3 = p[3];
        aR[0] = pack_bf16(f0.x, f0.y); aR[1] = pack_bf16(f0.z, f0.w);
        aR[2] = pack_bf16(f1.x, f1.y); aR[3] = pack_bf16(f1.z, f1.w);
        aR[4] = pack_bf16(f2.x, f2.y); aR[5] = pack_bf16(f2.z, f2.w);
        aR[6] = pack_bf16(f3.x, f3.y); aR[7] = pack_bf16(f3.z, f3.w);
    };
    auto stsA = [&](int buf) {
        uint8_t* sa = smem + G1_A(buf) + lr * RSTR + kh * 2;
        *(uint4*)(sa)      = make_uint4(aR[0], aR[1], aR[2], aR[3]);
        *(uint4*)(sa + 16) = make_uint4(aR[4], aR[5], aR[6], aR[7]);
    };
    auto issueB = [&](int c, int buf) {
        uint32_t d = sbase + G1_B(buf) + lr * RSTR + kh * 2;
        const __nv_bfloat16* s = bRow + (c << 5);
        cp16(d, s); cp16(d + 16, s + 8);
    };

    ldgA(0); stsA(0);
    issueB(0, 0); CP_COMMIT();
    issueB(1, 1); CP_COMMIT();
    __syncthreads();

    const int NC = K >> 5;
    for (int c = 0; c < NC; c++) {
        // Hoisted A prefetch: LDG latency overlaps the cp.async wait + barrier.
        if (c + 1 < NC) ldgA(c + 1);
        if (c == NC - 1) CP_WAIT0(); else CP_WAIT1();
        __syncthreads();
        if (c + 2 < NC) { issueB(c + 2, (c + 2) % 3); CP_COMMIT(); }
        core_compute(f, sbase, G1_A(c & 1), G1_B(c % 3), warp_m, warp_n, lane);
        if (c + 1 < NC) stsA((c + 1) & 1);
    }

#pragma unroll
    for (int mt = 0; mt < 2; mt++) {
        const int r0 = mBase + warp_m + mt * 16 + (lane >> 2);
#pragma unroll
        for (int nt = 0; nt < 8; nt++) {
            const int col = nBase + warp_n + nt * 8 + ((lane & 3) << 1);
            const float b0 = bias[col], b1 = bias[col + 1];
            if (r0 < M)
                *(uint32_t*)(C + (size_t)r0 * 256 + col) =
                    pack_bf16(fmaxf(f.acc[mt][nt][0] + b0, 0.f), fmaxf(f.acc[mt][nt][1] + b1, 0.f));
            if (r0 + 8 < M)
                *(uint32_t*)(C + (size_t)(r0 + 8) * 256 + col) =
                    pack_bf16(fmaxf(f.acc[mt][nt][2] + b0, 0.f), fmaxf(f.acc[mt][nt][3] + b1, 0.f));
        }
    }
}

// ---------------------------------------------------------------------------
// GEMM2: C[M,256] = bf16(relu(A_bf16[M,256] @ Bt[256,K]^T + bias))
// Full cp.async 3-stage on A and B, K-chunk 32.
// ---------------------------------------------------------------------------
__global__ __launch_bounds__(256) void hgemm2(
    const __nv_bfloat16* __restrict__ A, const __nv_bfloat16* __restrict__ Bt,
    const float* __restrict__ bias, __nv_bfloat16* __restrict__ C,
    int M, int K)
{
    extern __shared__ uint8_t smem[];
    const uint32_t sbase = smem_u32(smem);
    const int tid = threadIdx.x, lane = tid & 31, wid = tid >> 5;
    const int mBase = blockIdx.y << 7, nBase = blockIdx.x << 7;
    const int warp_m = (wid & 3) << 5, warp_n = (wid >> 2) << 6;

    const int lr = tid >> 1, kh = (tid & 1) << 4;
    const int asz = ((mBase + lr) < M) ? 16 : 0;
    const __nv_bfloat16* aRow = A + (size_t)(mBase + lr) * K + kh;
    const __nv_bfloat16* bRow = Bt + (size_t)(nBase + lr) * K + kh;

    Frag f; frag_zero(f);

    auto issueAB = [&](int c, int buf) {
        uint32_t da = sbase + G2_A(buf) + lr * RSTR + kh * 2;
        const __nv_bfloat16* sa = aRow + (c << 5);
        cp16z(da, sa, asz); cp16z(da + 16, sa + 8, asz);
        uint32_t db = sbase + G2_B(buf) + lr * RSTR + kh * 2;
        const __nv_bfloat16* sb = bRow + (c << 5);
        cp16(db, sb); cp16(db + 16, sb + 8);
    };

    issueAB(0, 0); CP_COMMIT();
    issueAB(1, 1); CP_COMMIT();

    const int NC = K >> 5;
    for (int c = 0; c < NC; c++) {
        if (c == NC - 1) CP_WAIT0(); else CP_WAIT1();
        __syncthreads();
        if (c + 2 < NC) { issueAB(c + 2, (c + 2) % 3); CP_COMMIT(); }
        core_compute(f, sbase, G2_A(c % 3), G2_B(c % 3), warp_m, warp_n, lane);
    }

#pragma unroll
    for (int mt = 0; mt < 2; mt++) {
        const int r0 = mBase + warp_m + mt * 16 + (lane >> 2);
#pragma unroll
        for (int nt = 0; nt < 8; nt++) {
            const int col = nBase + warp_n + nt * 8 + ((lane & 3) << 1);
            const float b0 = bias[col], b1 = bias[col + 1];
            if (r0 < M)
                *(uint32_t*)(C + (size_t)r0 * 256 + col) =
                    pack_bf16(fmaxf(f.acc[mt][nt][0] + b0, 0.f), fmaxf(f.acc[mt][nt][1] + b1, 0.f));
            if (r0 + 8 < M)
                *(uint32_t*)(C + (size_t)(r0 + 8) * 256 + col) =
                    pack_bf16(fmaxf(f.acc[mt][nt][2] + b0, 0.f), fmaxf(f.acc[mt][nt][3] + b1, 0.f));
        }
    }
}

// ---------------------------------------------------------------------------
// Edge GEMM: A rows gathered [h[parent]|h[child]] (K=512), cp.async 3-stage,
// CRF-masked fp32 output out[e*256 + r*16 + c].
// ---------------------------------------------------------------------------
__global__ __launch_bounds__(256) void hgemm_edge(
    const __nv_bfloat16* __restrict__ h, const __nv_bfloat16* __restrict__ Bt,
    const float* __restrict__ be,
    const int* __restrict__ parent, const int* __restrict__ child,
    const int* __restrict__ obs, const int* __restrict__ tl,
    float* __restrict__ out, int E)
{
    extern __shared__ uint8_t smem[];
    __shared__ int sPl[128], sCl[128], sOp[128], sOc[128];
    const uint32_t sbase = smem_u32(smem);
    const int tid = threadIdx.x, lane = tid & 31, wid = tid >> 5;
    const int mBase = blockIdx.y << 7, nBase = blockIdx.x << 7;
    const int warp_m = (wid & 3) << 5, warp_n = (wid >> 2) << 6;

    const int lr = tid >> 1, kh = (tid & 1) << 4;
    const int eA = mBase + lr;
    const bool ev = eA < E;
    const int asz = ev ? 16 : 0;
    const int pidx = ev ? parent[eA] : 0;
    const int cidx = ev ? child[eA] : 0;
    const __nv_bfloat16* pRow = h + (size_t)pidx * 256 + kh;
    const __nv_bfloat16* cRow = h + (size_t)cidx * 256 + kh;
    const __nv_bfloat16* bRow = Bt + (size_t)(nBase + lr) * 512 + kh;

    Frag f; frag_zero(f);

    auto issueAB = [&](int c, int buf) {
        uint32_t da = sbase + G2_A(buf) + lr * RSTR + kh * 2;
        const __nv_bfloat16* sa = ((c < 8) ? pRow : cRow) + ((c & 7) << 5);
        cp16z(da, sa, asz); cp16z(da + 16, sa + 8, asz);
        uint32_t db = sbase + G2_B(buf) + lr * RSTR + kh * 2;
        const __nv_bfloat16* sb = bRow + (c << 5);
        cp16(db, sb); cp16(db + 16, sb + 8);
    };

    issueAB(0, 0); CP_COMMIT();
    issueAB(1, 1); CP_COMMIT();

    const int NC = 16;  // K = 512
    for (int c = 0; c < NC; c++) {
        if (c == NC - 1) CP_WAIT0(); else CP_WAIT1();
        __syncthreads();
        if (c + 2 < NC) { issueAB(c + 2, (c + 2) % 3); CP_COMMIT(); }
        core_compute(f, sbase, G2_A(c % 3), G2_B(c % 3), warp_m, warp_n, lane);
    }

    // stage per-row CRF mask data
    if (tid < 128) {
        int e = mBase + tid;
        int pi = 0, ci = 0;
        if (e < E) { pi = parent[e]; ci = child[e]; }
        sPl[tid] = tl[pi]; sCl[tid] = tl[ci];
        sOp[tid] = obs[pi]; sOc[tid] = obs[ci];
    }
    __syncthreads();

    auto maskv = [&](float ep, int rloc, int rl, int cb) -> float {
        const int pl = sPl[rloc], cl = sCl[rloc];
        const int op = sOp[rloc], oc = sOc[rloc];
        if (op && oc) return (rl == pl && cb == cl) ? 0.f : AZf;
        if (oc)       return ep + ((rl == cl) ? 0.f : AZf);
        if (op)       return ep + ((cb == pl) ? 0.f : AZf);
        return ep;
    };

#pragma unroll
    for (int mt = 0; mt < 2; mt++) {
        const int rloc0 = warp_m + mt * 16 + (lane >> 2);
#pragma unroll
        for (int nt = 0; nt < 8; nt++) {
            const int col = nBase + warp_n + nt * 8 + ((lane & 3) << 1);
            const int rl = col >> 4, cb = col & 15;
            const int rl1 = (col + 1) >> 4, cb1 = (col + 1) & 15;
            const float b0 = be[col], b1 = be[col + 1];
            if (mBase + rloc0 < E) {
                float2 v;
                v.x = maskv(f.acc[mt][nt][0] + b0, rloc0, rl, cb);
                v.y = maskv(f.acc[mt][nt][1] + b1, rloc0, rl1, cb1);
                *(float2*)(out + (size_t)(mBase + rloc0) * 256 + col) = v;
            }
            if (mBase + rloc0 + 8 < E) {
                float2 v;
                v.x = maskv(f.acc[mt][nt][2] + b0, rloc0 + 8, rl, cb);
                v.y = maskv(f.acc[mt][nt][3] + b1, rloc0 + 8, rl1, cb1);
                *(float2*)(out + (size_t)(mBase + rloc0 + 8) * 256 + col) = v;
            }
        }
    }
}

// ---------------------------------------------------------------------------
// Unary: out[row,c] = obs ? (tl==c ? 0 : AZ) : h2[row]·Wu[:,c] + bu[c]
// Vectorized uint4 loads of h2.
// ---------------------------------------------------------------------------
__global__ __launch_bounds__(256) void unary_kernel(
    const __nv_bfloat16* __restrict__ h, const float* __restrict__ Wu,
    const float* __restrict__ bu, const int* __restrict__ obs,
    const int* __restrict__ tl, float* __restrict__ out, int N)
{
    __shared__ float sW[256 * 16];
    __shared__ float sH[16][260];
    const int tid = threadIdx.x;
    const float4* w4 = (const float4*)Wu;
    for (int i = tid; i < 1024; i += 256) ((float4*)sW)[i] = w4[i];
    const int row0 = blockIdx.x * 16;
    for (int i = tid; i < 512; i += 256) {
        const int r = i >> 5;
        const int c8 = (i & 31) << 3;
        uint4 v = make_uint4(0, 0, 0, 0);
        if (row0 + r < N)
            v = ((const uint4*)(h + (size_t)(row0 + r) * 256))[i & 31];
        uint32_t u[4] = {v.x, v.y, v.z, v.w};
#pragma unroll
        for (int j = 0; j < 4; j++) {
            __nv_bfloat162 b2 = *reinterpret_cast<__nv_bfloat162*>(&u[j]);
            sH[r][c8 + 2 * j]     = __bfloat162float(b2.x);
            sH[r][c8 + 2 * j + 1] = __bfloat162float(b2.y);
        }
    }
    __syncthreads();
    const int tx = tid & 15, ty = tid >> 4;
    const int row = row0 + ty;
    if (row >= N) return;
    float acc = 0.f;
#pragma unroll 8
    for (int k = 0; k < 256; k++) acc += sH[ty][k] * sW[k * 16 + tx];
    float v;
    if (obs[row]) v = (tl[row] == tx) ? 0.f : AZf;
    else          v = acc + bu[tx];
    out[(size_t)row * 16 + tx] = v;
}

// ---------------------------------------------------------------------------

extern "C" void kernel_launch(void* const* d_in, const int* in_sizes, int n_in,
                              void* d_out, int out_size)
{
    const float* features = (const float*)d_in[0];
    const int*   parent   = (const int*)  d_in[1];
    const int*   child    = (const int*)  d_in[2];
    const int*   obs      = (const int*)  d_in[3];
    const int*   tl       = (const int*)  d_in[4];
    const float* W1       = (const float*)d_in[5];
    const float* b1       = (const float*)d_in[6];
    const float* W2       = (const float*)d_in[7];
    const float* b2       = (const float*)d_in[8];
    const float* Wu       = (const float*)d_in[9];
    const float* bu       = (const float*)d_in[10];
    const float* We       = (const float*)d_in[11];
    const float* be       = (const float*)d_in[12];

    const int N = in_sizes[0] / 768;
    const int E = in_sizes[1];

    float* outU = (float*)d_out;
    float* outE = outU + (size_t)N * 16;

    __nv_bfloat16 *h1, *h2, *wt1, *wt2, *wet;
    cudaGetSymbolAddress((void**)&h1,  g_h1);
    cudaGetSymbolAddress((void**)&h2,  g_h2);
    cudaGetSymbolAddress((void**)&wt1, g_Wt1);
    cudaGetSymbolAddress((void**)&wt2, g_Wt2);
    cudaGetSymbolAddress((void**)&wet, g_Wet);

    cudaFuncSetAttribute(hgemm1,     cudaFuncAttributeMaxDynamicSharedMemorySize, SMEM_G1);
    cudaFuncSetAttribute(hgemm2,     cudaFuncAttributeMaxDynamicSharedMemorySize, SMEM_G2);
    cudaFuncSetAttribute(hgemm_edge, cudaFuncAttributeMaxDynamicSharedMemorySize, SMEM_G2);

    // Side stream + events, created once on the first (non-capture) call.
    static cudaStream_t s2 = nullptr;
    static cudaEvent_t ev0 = nullptr, evW = nullptr, ev1 = nullptr, ev2 = nullptr;
    if (!s2) {
        cudaStreamCreateWithFlags(&s2, cudaStreamNonBlocking);
        cudaEventCreateWithFlags(&ev0, cudaEventDisableTiming);
        cudaEventCreateWithFlags(&evW, cudaEventDisableTiming);
        cudaEventCreateWithFlags(&ev1, cudaEventDisableTiming);
        cudaEventCreateWithFlags(&ev2, cudaEventDisableTiming);
    }

    const int gM = (N + 127) / 128;
    const int gE = (E + 127) / 128;

    // Fork: wt2/wet transposes on s2 overlap wt1-transpose + hgemm1 on main.
    cudaEventRecord(ev0, 0);
    cudaStreamWaitEvent(s2, ev0, 0);
    transpose_w<<<dim3(8, 8),  dim3(32, 8), 0, s2>>>(W2, wt2, 256, 256);
    transpose_w<<<dim3(8, 16), dim3(32, 8), 0, s2>>>(We, wet, 512, 256);
    cudaEventRecord(evW, s2);

    transpose_w<<<dim3(8, 24), dim3(32, 8)>>>(W1, wt1, 768, 256);
    hgemm1<<<dim3(2, gM), 256, SMEM_G1>>>(features, wt1, b1, h1, N, 768);

    cudaStreamWaitEvent(0, evW, 0);     // wt2/wet ready before hgemm2/edge
    hgemm2<<<dim3(2, gM), 256, SMEM_G2>>>(h1, wt2, b2, h2, N, 256);
    cudaEventRecord(ev1, 0);

    // Fork: unary on s2 overlaps edge on main (both depend only on h2).
    cudaStreamWaitEvent(s2, ev1, 0);
    unary_kernel<<<(N + 15) / 16, 256, 0, s2>>>(h2, Wu, bu, obs, tl, outU, N);
    cudaEventRecord(ev2, s2);

    hgemm_edge<<<dim3(2, gE), 256, SMEM_G2>>>(h2, wet, be, parent, child, obs, tl, outE, E);
    cudaStreamWaitEvent(0, ev2, 0);     // join before harness's end-of-capture
}